// round 3
// baseline (speedup 1.0000x reference)
#include <cuda_runtime.h>

#define BB   16
#define CIN  32
#define COUT 32
#define HH   256
#define WW   256
#define RFW (BB*CIN*HH)    // 131072
#define RIV (BB*COUT*HH)   // 131072

// ---------------- scratch (device globals; no cudaMalloc) ----------------
__device__ float2 g_T1[129*16];                      // (cos, -sin) fwd, half-weight at w=0,128
__device__ float2 g_U1[129*16];                      // (coef*cos, -coef*sin) inv
__device__ float2 g_TW256[256];                      // e^{-2pi i a h0/256}, [a*16+h0]
__device__ float2 g_TW16[16];                        // e^{-2pi i t/16}
__device__ float2 g_wpack[512*32*32];                // [mode][i][o]
__device__ float2 g_G[(size_t)BB*CIN*HH*16];         // [b,i,h][ky]      16 MB
__device__ float2 g_Xft[BB*CIN*32*16];               // [b,i][kxidx][ky]
__device__ float2 g_Yft[BB*COUT*32*16];              // [b,o][kxidx][ky]
__device__ float  g_Zp[(size_t)BB*COUT*HH*32];       // [b,o,h][2ky|2ky+1] 16 MB

// ---------------- tables ----------------
__global__ void init_tables() {
    int idx = blockIdx.x * blockDim.x + threadIdx.x;
    if (idx < 2064) {                       // g_T1[w][ky]
        int w = idx >> 4, ky = idx & 15;
        int t = (ky * w) & 255;
        float s, c; sincospif(t * (1.0f/128.0f), &s, &c);
        float hw = (w == 0 || w == 128) ? 0.5f : 1.0f;
        g_T1[idx] = make_float2(hw * c, -hw * s);
    } else if (idx < 4128) {                // g_U1[w][ky]
        int j = idx - 2064;
        int w = j >> 4, ky = j & 15;
        int t = (ky * w) & 255;
        float s, c; sincospif(t * (1.0f/128.0f), &s, &c);
        float coef = ((ky == 0) ? 1.0f : 2.0f) * (1.0f/65536.0f);
        g_U1[j] = make_float2(coef * c, -coef * s);
    } else if (idx < 4384) {                // g_TW256[a*16+h0]
        int j = idx - 4128;
        int a = j >> 4, h0 = j & 15;
        int t = (a * h0) & 255;
        float s, c; sincospif(t * (1.0f/128.0f), &s, &c);
        g_TW256[j] = make_float2(c, -s);
    } else if (idx < 4400) {                // g_TW16[t]
        int t = idx - 4384;
        float s, c; sincospif(t * (1.0f/8.0f), &s, &c);
        g_TW16[t] = make_float2(c, -s);
    }
}

// ---------------- weight repack: [Cin][Cout][m1][m2] -> [mode][i][o] ----------------
__global__ void repack_w(const float* __restrict__ w1r, const float* __restrict__ w1i,
                         const float* __restrict__ w2r, const float* __restrict__ w2i) {
    int idx = blockIdx.x * blockDim.x + threadIdx.x;
    if (idx >= 512*1024) return;
    int o = idx & 31, i = (idx >> 5) & 31, mode = idx >> 10;
    int ky = mode & 15, kxidx = mode >> 4;
    int x = kxidx & 15;
    int src = ((i*32 + o)*16 + x)*16 + ky;
    float re = (kxidx < 16) ? w1r[src] : w2r[src];
    float im = (kxidx < 16) ? w1i[src] : w2i[src];
    g_wpack[idx] = make_float2(re, im);
}

// ---------------- stage 1: fwd w-DFT with mirror symmetry (K=129) ----------------
// se[w] = x[w]+x[256-w], so[w] = x[w]-x[256-w]; G_re = sum se*cos', G_im = sum so*(-sin)
__global__ __launch_bounds__(128) void fwd_wdft(const float* __restrict__ x) {
    extern __shared__ float fw_buf[];
    float*  se = fw_buf;                       // [129][66]
    float*  so = se + 129*66;                  // [129][66]
    float4* sT = (float4*)(so + 129*66);       // [129][8] = (c0,s0,c1,s1) per ky-pair
    int tid = threadIdx.x;

    const float4* t4 = (const float4*)g_T1;
    for (int i = tid; i < 129*8; i += 128) sT[i] = t4[i];

    const float* xb = x + (size_t)blockIdx.x * (64*256);
    int mir = (256 - tid) & 255;
    #pragma unroll 2
    for (int r = 0; r < 64; r++) {
        float a = xb[r*256 + tid];
        float b = xb[r*256 + mir];
        se[tid*66 + r] = a + b;
        so[tid*66 + r] = a - b;
    }
    if (tid < 64) {
        float v = xb[tid*256 + 128];
        se[128*66 + tid] = 2.0f * v;
        so[128*66 + tid] = 0.0f;
    }
    __syncthreads();

    int tm = tid >> 3, tn = tid & 7;           // tm: 4 rows, tn: ky pair (2tn,2tn+1)
    float aR0[4] = {}, aI0[4] = {}, aR1[4] = {}, aI1[4] = {};
    #pragma unroll 3
    for (int w = 0; w < 129; w++) {
        float2 e01 = *(const float2*)&se[w*66 + tm*4];
        float2 e23 = *(const float2*)&se[w*66 + tm*4 + 2];
        float2 o01 = *(const float2*)&so[w*66 + tm*4];
        float2 o23 = *(const float2*)&so[w*66 + tm*4 + 2];
        float4 t = sT[w*8 + tn];
        float e_[4] = {e01.x, e01.y, e23.x, e23.y};
        float o_[4] = {o01.x, o01.y, o23.x, o23.y};
        #pragma unroll
        for (int j = 0; j < 4; j++) {
            aR0[j] += e_[j] * t.x;
            aI0[j] += o_[j] * t.y;
            aR1[j] += e_[j] * t.z;
            aI1[j] += o_[j] * t.w;
        }
    }
    float* Gf = (float*)g_G;
    size_t rbase = (size_t)blockIdx.x*64 + tm*4;
    #pragma unroll
    for (int j = 0; j < 4; j++) {
        float4 v = make_float4(aR0[j], aI0[j], aR1[j], aI1[j]);
        *(float4*)&Gf[(rbase + j)*32 + tn*4] = v;
    }
}

// ---------------- stage 2: fwd h-DFT, radix-16 split ----------------
__global__ __launch_bounds__(256) void fwd_hdft() {
    extern __shared__ float2 fh_buf[];
    float2* sG  = fh_buf;            // [256][17]
    float2* sP  = sG + 256*17;       // [16][257]  (h0-major, inner a*16+ky)
    float2* sTW = sP + 16*257;       // 256
    float2* s16 = sTW + 256;         // 16
    int bi = blockIdx.x, tid = threadIdx.x;

    const float2* Gsrc = &g_G[(size_t)bi * 4096];
    for (int i = tid; i < 4096; i += 256) sG[(i >> 4)*17 + (i & 15)] = Gsrc[i];
    sTW[tid & 255] = g_TW256[tid & 255];
    if (tid < 16) s16[tid] = g_TW16[tid];
    __syncthreads();

    int h0 = tid >> 4, ky = tid & 15;
    float2 P[16];
    #pragma unroll
    for (int a = 0; a < 16; a++) P[a] = make_float2(0.f, 0.f);
    #pragma unroll
    for (int h1 = 0; h1 < 16; h1++) {
        float2 g = sG[(h1*16 + h0)*17 + ky];
        #pragma unroll
        for (int a = 0; a < 16; a++) {
            float2 t = s16[(a*h1) & 15];
            P[a].x += g.x*t.x - g.y*t.y;
            P[a].y += g.x*t.y + g.y*t.x;
        }
    }
    #pragma unroll
    for (int a = 0; a < 16; a++) sP[h0*257 + a*16 + ky] = P[a];
    __syncthreads();

    int a = h0;   // thread now handles bins a and 240+a (via index 16+a)
    float2 x1 = make_float2(0.f, 0.f), x2 = make_float2(0.f, 0.f);
    #pragma unroll
    for (int hh = 0; hh < 16; hh++) {
        float2 p  = sP[hh*257 + a*16 + ky];
        float2 t1 = sTW[a*16 + hh];                 // e^{-2pi i a hh/256}
        float2 q;
        q.x = p.x*t1.x - p.y*t1.y;
        q.y = p.x*t1.y + p.y*t1.x;
        x1.x += q.x; x1.y += q.y;
        float2 c = s16[hh];                         // tw2 = t1 * conj(s16[hh])
        x2.x += q.x*c.x + q.y*c.y;
        x2.y += q.y*c.x - q.x*c.y;
    }
    g_Xft[(bi*32 + a)*16 + ky]      = x1;
    g_Xft[(bi*32 + 16 + a)*16 + ky] = x2;
}

// ---------------- stage 3: channel mix (complex 32x32 per mode) ----------------
__global__ __launch_bounds__(256) void chan_mix() {
    __shared__ float2 sW[32*32];
    __shared__ float2 sX[16*32];
    int mode  = blockIdx.x;
    int kxidx = mode >> 4, ky = mode & 15;
    int tid   = threadIdx.x;

    #pragma unroll
    for (int p = 0; p < 4; p++) sW[tid + p*256] = g_wpack[mode*1024 + tid + p*256];
    sX[tid % 512]         = g_Xft[(tid*32 + kxidx)*16 + ky];
    sX[(tid + 256) % 512] = g_Xft[((tid + 256)*32 + kxidx)*16 + ky];
    __syncthreads();

    int o = tid & 31, b0 = tid >> 5;
    float2 acc0 = make_float2(0.f, 0.f), acc1 = make_float2(0.f, 0.f);
    #pragma unroll
    for (int i = 0; i < 32; i++) {
        float2 wv = sW[i*32 + o];
        float2 x0 = sX[b0*32 + i];
        float2 x1 = sX[(b0 + 8)*32 + i];
        acc0.x += x0.x*wv.x - x0.y*wv.y; acc0.y += x0.x*wv.y + x0.y*wv.x;
        acc1.x += x1.x*wv.x - x1.y*wv.y; acc1.y += x1.x*wv.y + x1.y*wv.x;
    }
    g_Yft[((b0*32 + o)*32 + kxidx)*16 + ky]       = acc0;
    g_Yft[(((b0 + 8)*32 + o)*32 + kxidx)*16 + ky] = acc1;
}

// ---------------- stage 4: inverse h-DFT, radix-16 split ----------------
__global__ __launch_bounds__(256) void inv_hdft() {
    __shared__ float2 sY[512];
    __shared__ float2 sTW[256];
    __shared__ float2 s16[16];
    int bo = blockIdx.x, tid = threadIdx.x;
    sY[tid]       = g_Yft[bo*512 + tid];
    sY[tid + 256] = g_Yft[bo*512 + tid + 256];
    sTW[tid & 255] = g_TW256[tid & 255];
    if (tid < 16) s16[tid] = g_TW16[tid];
    __syncthreads();

    int h0 = tid >> 4, ky = tid & 15;
    float2 w16 = s16[h0];                            // e^{-2pi i h0/16}
    float2 Q[16];
    #pragma unroll
    for (int j = 0; j < 16; j++) {
        float2 t = sTW[j*16 + h0];
        float2 u = make_float2(t.x, -t.y);           // e^{+2pi i j h0/256}
        float2 v;                                    // e^{+2pi i (240+j) h0/256} = u * w16
        v.x = u.x*w16.x - u.y*w16.y;
        v.y = u.x*w16.y + u.y*w16.x;
        float2 y1 = sY[j*16 + ky], y2 = sY[(16 + j)*16 + ky];
        Q[j].x = y1.x*u.x - y1.y*u.y + y2.x*v.x - y2.y*v.y;
        Q[j].y = y1.x*u.y + y1.y*u.x + y2.x*v.y + y2.y*v.x;
    }
    float* Zb = &g_Zp[((size_t)bo*256 + h0)*32 + 2*ky];
    #pragma unroll
    for (int h1 = 0; h1 < 16; h1++) {
        float2 acc = make_float2(0.f, 0.f);
        #pragma unroll
        for (int j = 0; j < 16; j++) {
            float2 t = s16[(j*h1) & 15];             // conj -> e^{+2pi i j h1/16}
            acc.x += Q[j].x*t.x + Q[j].y*t.y;
            acc.y += Q[j].y*t.x - Q[j].x*t.y;
        }
        *(float2*)&Zb[h1*16*32] = acc;
    }
}

// ---------------- stage 5: inverse w-DFT with mirror symmetry (K=16 complex) ----------------
__global__ __launch_bounds__(256) void inv_wdft(float* __restrict__ out) {
    __shared__ float  sZ[64*36];
    __shared__ float4 sU[129*9];
    int tid = threadIdx.x;
    int r0 = blockIdx.x * 64;

    const float4* zp4 = (const float4*)&g_Zp[(size_t)r0*32];
    for (int i = tid; i < 512; i += 256) {
        int r = i >> 3, c = i & 7;
        *(float4*)&sZ[r*36 + c*4] = zp4[i];
    }
    const float4* u4 = (const float4*)g_U1;
    for (int i = tid; i < 129*8; i += 256) {
        int w = i >> 3, k = i & 7;
        sU[w*9 + k] = u4[i];
    }
    __syncthreads();

    int tm = tid >> 4, tn = tid & 15;
    const float* zbase = &sZ[tm*4*36];
    #pragma unroll
    for (int it = 0; it < 9; it++) {
        int w = tn + it*16;
        if (w <= 128) {
            float C[4] = {}, S[4] = {};
            #pragma unroll
            for (int kp = 0; kp < 8; kp++) {
                float4 u = sU[w*9 + kp];             // (c0,s0,c1,s1)
                #pragma unroll
                for (int j = 0; j < 4; j++) {
                    float4 z = *(const float4*)&zbase[j*36 + kp*4];  // (zr0,zi0,zr1,zi1)
                    C[j] += z.x*u.x + z.z*u.z;
                    S[j] += z.y*u.y + z.w*u.w;
                }
            }
            #pragma unroll
            for (int j = 0; j < 4; j++) {
                size_t R = (size_t)(r0 + tm*4 + j) * 256;
                out[R + w] = C[j] + S[j];
                if (w > 0 && w < 128) out[R + 256 - w] = C[j] - S[j];
            }
        }
    }
}

// ---------------- launch ----------------
extern "C" void kernel_launch(void* const* d_in, const int* in_sizes, int n_in,
                              void* d_out, int out_size) {
    const float* x   = (const float*)d_in[0];
    const float* w1r = (const float*)d_in[1];
    const float* w1i = (const float*)d_in[2];
    const float* w2r = (const float*)d_in[3];
    const float* w2i = (const float*)d_in[4];
    float* out = (float*)d_out;

    const int FW_SMEM = (129*66*2)*4 + 129*8*16;             // 84624
    const int FH_SMEM = (256*17 + 16*257 + 256 + 16)*8;      // 69888
    cudaFuncSetAttribute(fwd_wdft, cudaFuncAttributeMaxDynamicSharedMemorySize, FW_SMEM);
    cudaFuncSetAttribute(fwd_hdft, cudaFuncAttributeMaxDynamicSharedMemorySize, FH_SMEM);

    init_tables<<<18, 256>>>();
    repack_w<<<2048, 256>>>(w1r, w1i, w2r, w2i);
    fwd_wdft<<<RFW/64, 128, FW_SMEM>>>(x);
    fwd_hdft<<<BB*CIN, 256, FH_SMEM>>>();
    chan_mix<<<512, 256>>>();
    inv_hdft<<<BB*COUT, 256>>>();
    inv_wdft<<<RIV/64, 256>>>(out);
}

// round 5
// speedup vs baseline: 2.1066x; 2.1066x over previous
#include <cuda_runtime.h>
#include <cstdint>

#define BB   16
#define CIN  32
#define COUT 32
#define HH   256
#define WW   256
#define RFW (BB*CIN*HH)    // 131072
#define RIV (BB*COUT*HH)   // 131072

// ---------------- scratch (device globals; no cudaMalloc) ----------------
__device__ float2 g_B1[32*32*4];                     // stage1 B frag pairs [kstep32][n32][c4] = (T[k][n], T[k+4][n])
__device__ float2 g_B5[4*256*4];                     // stage5 B frag pairs [kstep4][w256][c4] = (U[k][w], U[k+4][w])
__device__ float2 g_TW256[256];                      // e^{-2pi i a h0/256}, [a*16+h0]
__device__ float2 g_TW16[16];                        // e^{-2pi i t/16}
__device__ float2 g_wpack[512*32*32];                // [mode][i][o]
__device__ float2 g_G[(size_t)BB*CIN*HH*16];         // [b,i,h][ky]      16 MB
__device__ float2 g_Xft[BB*CIN*32*16];               // [b,i][kxidx][ky]
__device__ float2 g_Yft[BB*COUT*32*16];              // [b,o][kxidx][ky]
__device__ float  g_Zp[(size_t)BB*COUT*HH*32];       // [b,o,h][2ky|2ky+1] 16 MB

__device__ __forceinline__ float tf32rna(float x) {
    uint32_t u; asm("cvt.rna.tf32.f32 %0, %1;" : "=r"(u) : "f"(x));
    return __uint_as_float(u);
}
__device__ __forceinline__ void mma_tf32(float d[4], uint32_t a0, uint32_t a1, uint32_t a2, uint32_t a3,
                                         uint32_t b0, uint32_t b1) {
    asm volatile(
        "mma.sync.aligned.m16n8k8.row.col.f32.tf32.tf32.f32 "
        "{%0,%1,%2,%3}, {%4,%5,%6,%7}, {%8,%9}, {%0,%1,%2,%3};"
        : "+f"(d[0]), "+f"(d[1]), "+f"(d[2]), "+f"(d[3])
        : "r"(a0), "r"(a1), "r"(a2), "r"(a3), "r"(b0), "r"(b1));
}

// ---------------- tables ----------------
__global__ void init_tables() {
    int idx = blockIdx.x * blockDim.x + threadIdx.x;
    if (idx < 4096) {                        // g_B1[kstep][n][c]
        int c = idx & 3, n = (idx >> 2) & 31, kstep = idx >> 7;
        int ky = n >> 1;
        int k0 = kstep*8 + c, k1 = k0 + 4;
        int t0 = (ky * k0) & 255, t1 = (ky * k1) & 255;
        float s0, c0, s1, c1;
        sincospif(t0 * (1.0f/128.0f), &s0, &c0);
        sincospif(t1 * (1.0f/128.0f), &s1, &c1);
        float v0 = (n & 1) ? -s0 : c0;
        float v1 = (n & 1) ? -s1 : c1;
        g_B1[idx] = make_float2(tf32rna(v0), tf32rna(v1));
    } else if (idx < 8192) {                 // g_B5[kstep][w][c]
        int j = idx - 4096;
        int c = j & 3, w = (j >> 2) & 255, kstep = j >> 10;
        int k0 = kstep*8 + c, k1 = k0 + 4;
        int ky0 = k0 >> 1, ky1 = k1 >> 1;
        int t0 = (ky0 * w) & 255, t1 = (ky1 * w) & 255;
        float s0, c0, s1, c1;
        sincospif(t0 * (1.0f/128.0f), &s0, &c0);
        sincospif(t1 * (1.0f/128.0f), &s1, &c1);
        float cf0 = ((ky0 == 0) ? 1.0f : 2.0f) * (1.0f/65536.0f);
        float cf1 = ((ky1 == 0) ? 1.0f : 2.0f) * (1.0f/65536.0f);
        float v0 = (k0 & 1) ? -cf0 * s0 : cf0 * c0;
        float v1 = (k1 & 1) ? -cf1 * s1 : cf1 * c1;
        g_B5[j] = make_float2(tf32rna(v0), tf32rna(v1));
    } else if (idx < 8448) {                 // g_TW256[a*16+h0]
        int j = idx - 8192;
        int a = j >> 4, h0 = j & 15;
        int t = (a * h0) & 255;
        float s, c; sincospif(t * (1.0f/128.0f), &s, &c);
        g_TW256[j] = make_float2(c, -s);
    } else if (idx < 8464) {                 // g_TW16[t]
        int t = idx - 8448;
        float s, c; sincospif(t * (1.0f/8.0f), &s, &c);
        g_TW16[t] = make_float2(c, -s);
    }
}

// ---------------- weight repack: [Cin][Cout][m1][m2] -> [mode][i][o] ----------------
__global__ void repack_w(const float* __restrict__ w1r, const float* __restrict__ w1i,
                         const float* __restrict__ w2r, const float* __restrict__ w2i) {
    int idx = blockIdx.x * blockDim.x + threadIdx.x;
    if (idx >= 512*1024) return;
    int o = idx & 31, i = (idx >> 5) & 31, mode = idx >> 10;
    int ky = mode & 15, kxidx = mode >> 4;
    int x = kxidx & 15;
    int src = ((i*32 + o)*16 + x)*16 + ky;
    float re = (kxidx < 16) ? w1r[src] : w2r[src];
    float im = (kxidx < 16) ? w1i[src] : w2i[src];
    g_wpack[idx] = make_float2(re, im);
}

// ---------------- stage 1: fwd w-DFT via mma.sync tf32 (CTA: M=128, N=32, K=256) ----------------
__global__ __launch_bounds__(256) void fwd_wdft_mma(const float* __restrict__ x) {
    extern __shared__ float s1[];
    float*  sA = s1;                         // [128][68]
    float2* sB = (float2*)(s1 + 128*68);     // 4096 float2
    int tid = threadIdx.x, wid = tid >> 5, lane = tid & 31;
    int ln4 = lane >> 2, lc = lane & 3;

    const float2* gB = (const float2*)g_B1;
    for (int i = tid; i < 4096; i += 256) sB[i] = gB[i];

    const float* xb = x + (size_t)blockIdx.x * (128*256);
    float d[4][4] = {};
    int r0 = wid * 16;

    for (int kt = 0; kt < 4; kt++) {
        __syncthreads();
        #pragma unroll
        for (int p = 0; p < 8; p++) {
            int i = tid + p*256;
            int row = i >> 4, c4 = i & 15;
            float4 v = *(const float4*)&xb[row*256 + kt*64 + c4*4];
            v.x = tf32rna(v.x); v.y = tf32rna(v.y); v.z = tf32rna(v.z); v.w = tf32rna(v.w);
            *(float4*)&sA[row*68 + c4*4] = v;
        }
        __syncthreads();
        #pragma unroll
        for (int ks = 0; ks < 8; ks++) {
            int kc = ks*8;
            uint32_t a0 = __float_as_uint(sA[(r0 + ln4     )*68 + kc + lc    ]);
            uint32_t a1 = __float_as_uint(sA[(r0 + ln4 +  8)*68 + kc + lc    ]);
            uint32_t a2 = __float_as_uint(sA[(r0 + ln4     )*68 + kc + lc + 4]);
            uint32_t a3 = __float_as_uint(sA[(r0 + ln4 +  8)*68 + kc + lc + 4]);
            int gks = kt*8 + ks;
            #pragma unroll
            for (int nt = 0; nt < 4; nt++) {
                float2 b = sB[(gks*32 + nt*8 + ln4)*4 + lc];
                mma_tf32(d[nt], a0, a1, a2, a3, __float_as_uint(b.x), __float_as_uint(b.y));
            }
        }
    }
    float* Gf = (float*)g_G;
    size_t rowg = (size_t)blockIdx.x*128 + r0 + ln4;
    #pragma unroll
    for (int nt = 0; nt < 4; nt++) {
        int col = nt*8 + 2*lc;
        *(float2*)&Gf[rowg*32 + col]       = make_float2(d[nt][0], d[nt][1]);
        *(float2*)&Gf[(rowg + 8)*32 + col] = make_float2(d[nt][2], d[nt][3]);
    }
}

// ---------------- stage 2: fwd h-DFT, radix-16 split ----------------
__global__ __launch_bounds__(256) void fwd_hdft() {
    extern __shared__ float2 fh_buf[];
    float2* sG  = fh_buf;            // [256][17]
    float2* sP  = sG + 256*17;       // [16][257]
    float2* sTW = sP + 16*257;       // 256
    float2* s16 = sTW + 256;         // 16
    int bi = blockIdx.x, tid = threadIdx.x;

    const float2* Gsrc = &g_G[(size_t)bi * 4096];
    for (int i = tid; i < 4096; i += 256) sG[(i >> 4)*17 + (i & 15)] = Gsrc[i];
    sTW[tid & 255] = g_TW256[tid & 255];
    if (tid < 16) s16[tid] = g_TW16[tid];
    __syncthreads();

    int h0 = tid >> 4, ky = tid & 15;
    float2 P[16];
    #pragma unroll
    for (int a = 0; a < 16; a++) P[a] = make_float2(0.f, 0.f);
    #pragma unroll
    for (int h1 = 0; h1 < 16; h1++) {
        float2 g = sG[(h1*16 + h0)*17 + ky];
        #pragma unroll
        for (int a = 0; a < 16; a++) {
            float2 t = s16[(a*h1) & 15];
            P[a].x += g.x*t.x - g.y*t.y;
            P[a].y += g.x*t.y + g.y*t.x;
        }
    }
    #pragma unroll
    for (int a = 0; a < 16; a++) sP[h0*257 + a*16 + ky] = P[a];
    __syncthreads();

    int a = h0;
    float2 x1 = make_float2(0.f, 0.f), x2 = make_float2(0.f, 0.f);
    #pragma unroll
    for (int hh = 0; hh < 16; hh++) {
        float2 p  = sP[hh*257 + a*16 + ky];
        float2 t1 = sTW[a*16 + hh];
        float2 q;
        q.x = p.x*t1.x - p.y*t1.y;
        q.y = p.x*t1.y + p.y*t1.x;
        x1.x += q.x; x1.y += q.y;
        float2 c = s16[hh];
        x2.x += q.x*c.x + q.y*c.y;
        x2.y += q.y*c.x - q.x*c.y;
    }
    g_Xft[(bi*32 + a)*16 + ky]      = x1;
    g_Xft[(bi*32 + 16 + a)*16 + ky] = x2;
}

// ---------------- stage 3: channel mix (complex 32x32 per mode) ----------------
__global__ __launch_bounds__(256) void chan_mix() {
    __shared__ float2 sW[32*32];
    __shared__ float2 sX[16*32];
    int mode  = blockIdx.x;
    int kxidx = mode >> 4, ky = mode & 15;
    int tid   = threadIdx.x;

    #pragma unroll
    for (int p = 0; p < 4; p++) sW[tid + p*256] = g_wpack[mode*1024 + tid + p*256];
    sX[tid % 512]         = g_Xft[(tid*32 + kxidx)*16 + ky];
    sX[(tid + 256) % 512] = g_Xft[((tid + 256)*32 + kxidx)*16 + ky];
    __syncthreads();

    int o = tid & 31, b0 = tid >> 5;
    float2 acc0 = make_float2(0.f, 0.f), acc1 = make_float2(0.f, 0.f);
    #pragma unroll
    for (int i = 0; i < 32; i++) {
        float2 wv = sW[i*32 + o];
        float2 x0 = sX[b0*32 + i];
        float2 x1 = sX[(b0 + 8)*32 + i];
        acc0.x += x0.x*wv.x - x0.y*wv.y; acc0.y += x0.x*wv.y + x0.y*wv.x;
        acc1.x += x1.x*wv.x - x1.y*wv.y; acc1.y += x1.x*wv.y + x1.y*wv.x;
    }
    g_Yft[((b0*32 + o)*32 + kxidx)*16 + ky]       = acc0;
    g_Yft[(((b0 + 8)*32 + o)*32 + kxidx)*16 + ky] = acc1;
}

// ---------------- stage 4: inverse h-DFT, radix-16 split ----------------
__global__ __launch_bounds__(256) void inv_hdft() {
    __shared__ float2 sY[512];
    __shared__ float2 sTW[256];
    __shared__ float2 s16[16];
    int bo = blockIdx.x, tid = threadIdx.x;
    sY[tid]       = g_Yft[bo*512 + tid];
    sY[tid + 256] = g_Yft[bo*512 + tid + 256];
    sTW[tid & 255] = g_TW256[tid & 255];
    if (tid < 16) s16[tid] = g_TW16[tid];
    __syncthreads();

    int h0 = tid >> 4, ky = tid & 15;
    float2 w16 = s16[h0];
    float2 Q[16];
    #pragma unroll
    for (int j = 0; j < 16; j++) {
        float2 t = sTW[j*16 + h0];
        float2 u = make_float2(t.x, -t.y);
        float2 v;
        v.x = u.x*w16.x - u.y*w16.y;
        v.y = u.x*w16.y + u.y*w16.x;
        float2 y1 = sY[j*16 + ky], y2 = sY[(16 + j)*16 + ky];
        Q[j].x = y1.x*u.x - y1.y*u.y + y2.x*v.x - y2.y*v.y;
        Q[j].y = y1.x*u.y + y1.y*u.x + y2.x*v.y + y2.y*v.x;
    }
    float* Zb = &g_Zp[((size_t)bo*256 + h0)*32 + 2*ky];
    #pragma unroll
    for (int h1 = 0; h1 < 16; h1++) {
        float2 acc = make_float2(0.f, 0.f);
        #pragma unroll
        for (int j = 0; j < 16; j++) {
            float2 t = s16[(j*h1) & 15];
            acc.x += Q[j].x*t.x + Q[j].y*t.y;
            acc.y += Q[j].y*t.x - Q[j].x*t.y;
        }
        *(float2*)&Zb[h1*16*32] = acc;
    }
}

// ---------------- stage 5: inverse w-DFT via mma.sync tf32 (CTA: M=32, N=256, K=32) ----------------
__global__ __launch_bounds__(256) void inv_wdft_mma(float* __restrict__ out) {
    __shared__ float  sA[32*36];
    __shared__ float2 sB[4096];
    int tid = threadIdx.x, wid = tid >> 5, lane = tid & 31;
    int ln4 = lane >> 2, lc = lane & 3;
    int warpM = wid >> 2, warpN = wid & 3;

    const float2* gB = (const float2*)g_B5;
    #pragma unroll
    for (int p = 0; p < 16; p++) sB[tid + p*256] = gB[tid + p*256];

    const float* zb = g_Zp + (size_t)blockIdx.x * (32*32);
    {
        int i = tid;   // 256 float4 total
        int row = i >> 3, c4 = i & 7;
        float4 v = *(const float4*)&zb[row*32 + c4*4];
        v.x = tf32rna(v.x); v.y = tf32rna(v.y); v.z = tf32rna(v.z); v.w = tf32rna(v.w);
        *(float4*)&sA[row*36 + c4*4] = v;
    }
    __syncthreads();

    int r0 = warpM * 16, n00 = warpN * 64;
    float d[8][4] = {};
    #pragma unroll
    for (int ks = 0; ks < 4; ks++) {
        int kc = ks*8;
        uint32_t a0 = __float_as_uint(sA[(r0 + ln4    )*36 + kc + lc    ]);
        uint32_t a1 = __float_as_uint(sA[(r0 + ln4 + 8)*36 + kc + lc    ]);
        uint32_t a2 = __float_as_uint(sA[(r0 + ln4    )*36 + kc + lc + 4]);
        uint32_t a3 = __float_as_uint(sA[(r0 + ln4 + 8)*36 + kc + lc + 4]);
        #pragma unroll
        for (int nt = 0; nt < 8; nt++) {
            float2 b = sB[(ks*256 + n00 + nt*8 + ln4)*4 + lc];
            mma_tf32(d[nt], a0, a1, a2, a3, __float_as_uint(b.x), __float_as_uint(b.y));
        }
    }
    size_t rowg = (size_t)blockIdx.x*32 + r0 + ln4;
    float* o0 = out + rowg*256;
    float* o1 = out + (rowg + 8)*256;
    #pragma unroll
    for (int nt = 0; nt < 8; nt++) {
        int col = n00 + nt*8 + 2*lc;
        *(float2*)&o0[col] = make_float2(d[nt][0], d[nt][1]);
        *(float2*)&o1[col] = make_float2(d[nt][2], d[nt][3]);
    }
}

// ---------------- launch ----------------
extern "C" void kernel_launch(void* const* d_in, const int* in_sizes, int n_in,
                              void* d_out, int out_size) {
    const float* x   = (const float*)d_in[0];
    const float* w1r = (const float*)d_in[1];
    const float* w1i = (const float*)d_in[2];
    const float* w2r = (const float*)d_in[3];
    const float* w2i = (const float*)d_in[4];
    float* out = (float*)d_out;

    const int FW_SMEM = (128*68)*4 + 4096*8;                 // 34816 + 32768 = 67584
    const int FH_SMEM = (256*17 + 16*257 + 256 + 16) * 8;    // 69888
    cudaFuncSetAttribute(fwd_wdft_mma, cudaFuncAttributeMaxDynamicSharedMemorySize, FW_SMEM);
    cudaFuncSetAttribute(fwd_hdft,     cudaFuncAttributeMaxDynamicSharedMemorySize, FH_SMEM);

    init_tables<<<34, 256>>>();
    repack_w<<<2048, 256>>>(w1r, w1i, w2r, w2i);
    fwd_wdft_mma<<<RFW/128, 256, FW_SMEM>>>(x);
    fwd_hdft<<<BB*CIN, 256, FH_SMEM>>>();
    chan_mix<<<512, 256>>>();
    inv_hdft<<<BB*COUT, 256>>>();
    inv_wdft_mma<<<RIV/32, 256>>>(out);
}

// round 6
// speedup vs baseline: 2.3599x; 1.1202x over previous
#include <cuda_runtime.h>
#include <cstdint>

#define BB   16
#define CIN  32
#define COUT 32
#define HH   256
#define WW   256
#define RFW (BB*CIN*HH)    // 131072
#define RIV (BB*COUT*HH)   // 131072

// ---------------- scratch (device globals; no cudaMalloc) ----------------
__device__ float2 g_B1[32*32*4];                     // stage1 B frag pairs [kstep32][n32][c4]
__device__ float2 g_B5[4*256*4];                     // stage5 B frag pairs [kstep4][w256][c4]
__device__ float2 g_TW256[256];                      // e^{-2pi i a h0/256}, [a*16+h0]
__device__ float2 g_TW16[16];                        // e^{-2pi i t/16}
__device__ float2 g_wpack[512*32*32];                // [mode][i][o]
__device__ float2 g_G[(size_t)BB*CIN*HH*16];         // [b,i,h][ky]      16 MB
__device__ float2 g_Xft[BB*CIN*32*16];               // [b,i][kxidx][ky]
__device__ float2 g_Yft[BB*COUT*32*16];              // [b,o][kxidx][ky]

__device__ __forceinline__ float tf32rna(float x) {
    uint32_t u; asm("cvt.rna.tf32.f32 %0, %1;" : "=r"(u) : "f"(x));
    return __uint_as_float(u);
}
__device__ __forceinline__ void mma_tf32(float d[4], uint32_t a0, uint32_t a1, uint32_t a2, uint32_t a3,
                                         uint32_t b0, uint32_t b1) {
    asm volatile(
        "mma.sync.aligned.m16n8k8.row.col.f32.tf32.tf32.f32 "
        "{%0,%1,%2,%3}, {%4,%5,%6,%7}, {%8,%9}, {%0,%1,%2,%3};"
        : "+f"(d[0]), "+f"(d[1]), "+f"(d[2]), "+f"(d[3])
        : "r"(a0), "r"(a1), "r"(a2), "r"(a3), "r"(b0), "r"(b1));
}

// ---------------- tables ----------------
__global__ void init_tables() {
    int idx = blockIdx.x * blockDim.x + threadIdx.x;
    if (idx < 4096) {                        // g_B1[kstep][n][c]
        int c = idx & 3, n = (idx >> 2) & 31, kstep = idx >> 7;
        int ky = n >> 1;
        int k0 = kstep*8 + c, k1 = k0 + 4;
        int t0 = (ky * k0) & 255, t1 = (ky * k1) & 255;
        float s0, c0, s1, c1;
        sincospif(t0 * (1.0f/128.0f), &s0, &c0);
        sincospif(t1 * (1.0f/128.0f), &s1, &c1);
        float v0 = (n & 1) ? -s0 : c0;
        float v1 = (n & 1) ? -s1 : c1;
        g_B1[idx] = make_float2(tf32rna(v0), tf32rna(v1));
    } else if (idx < 8192) {                 // g_B5[kstep][w][c]
        int j = idx - 4096;
        int c = j & 3, w = (j >> 2) & 255, kstep = j >> 10;
        int k0 = kstep*8 + c, k1 = k0 + 4;
        int ky0 = k0 >> 1, ky1 = k1 >> 1;
        int t0 = (ky0 * w) & 255, t1 = (ky1 * w) & 255;
        float s0, c0, s1, c1;
        sincospif(t0 * (1.0f/128.0f), &s0, &c0);
        sincospif(t1 * (1.0f/128.0f), &s1, &c1);
        float cf0 = ((ky0 == 0) ? 1.0f : 2.0f) * (1.0f/65536.0f);
        float cf1 = ((ky1 == 0) ? 1.0f : 2.0f) * (1.0f/65536.0f);
        float v0 = (k0 & 1) ? -cf0 * s0 : cf0 * c0;
        float v1 = (k1 & 1) ? -cf1 * s1 : cf1 * c1;
        g_B5[j] = make_float2(tf32rna(v0), tf32rna(v1));
    } else if (idx < 8448) {                 // g_TW256[a*16+h0]
        int j = idx - 8192;
        int a = j >> 4, h0 = j & 15;
        int t = (a * h0) & 255;
        float s, c; sincospif(t * (1.0f/128.0f), &s, &c);
        g_TW256[j] = make_float2(c, -s);
    } else if (idx < 8464) {                 // g_TW16[t]
        int t = idx - 8448;
        float s, c; sincospif(t * (1.0f/8.0f), &s, &c);
        g_TW16[t] = make_float2(c, -s);
    }
}

// ---------------- weight repack ----------------
__global__ void repack_w(const float* __restrict__ w1r, const float* __restrict__ w1i,
                         const float* __restrict__ w2r, const float* __restrict__ w2i) {
    int idx = blockIdx.x * blockDim.x + threadIdx.x;
    if (idx >= 512*1024) return;
    int o = idx & 31, i = (idx >> 5) & 31, mode = idx >> 10;
    int ky = mode & 15, kxidx = mode >> 4;
    int x = kxidx & 15;
    int src = ((i*32 + o)*16 + x)*16 + ky;
    float re = (kxidx < 16) ? w1r[src] : w2r[src];
    float im = (kxidx < 16) ? w1i[src] : w2i[src];
    g_wpack[idx] = make_float2(re, im);
}

// ---------------- stage 1: fwd w-DFT via mma.sync tf32 (CTA: M=128, N=32, K=256) ----------------
__global__ __launch_bounds__(256) void fwd_wdft_mma(const float* __restrict__ x) {
    extern __shared__ float s1[];
    float*  sA = s1;                         // [128][68]
    float2* sB = (float2*)(s1 + 128*68);     // 4096 float2
    int tid = threadIdx.x, wid = tid >> 5, lane = tid & 31;
    int ln4 = lane >> 2, lc = lane & 3;

    const float2* gB = (const float2*)g_B1;
    for (int i = tid; i < 4096; i += 256) sB[i] = gB[i];

    const float* xb = x + (size_t)blockIdx.x * (128*256);
    float d[4][4] = {};
    int r0 = wid * 16;

    for (int kt = 0; kt < 4; kt++) {
        __syncthreads();
        #pragma unroll
        for (int p = 0; p < 8; p++) {
            int i = tid + p*256;
            int row = i >> 4, c4 = i & 15;
            float4 v = *(const float4*)&xb[row*256 + kt*64 + c4*4];
            v.x = tf32rna(v.x); v.y = tf32rna(v.y); v.z = tf32rna(v.z); v.w = tf32rna(v.w);
            *(float4*)&sA[row*68 + c4*4] = v;
        }
        __syncthreads();
        #pragma unroll
        for (int ks = 0; ks < 8; ks++) {
            int kc = ks*8;
            uint32_t a0 = __float_as_uint(sA[(r0 + ln4     )*68 + kc + lc    ]);
            uint32_t a1 = __float_as_uint(sA[(r0 + ln4 +  8)*68 + kc + lc    ]);
            uint32_t a2 = __float_as_uint(sA[(r0 + ln4     )*68 + kc + lc + 4]);
            uint32_t a3 = __float_as_uint(sA[(r0 + ln4 +  8)*68 + kc + lc + 4]);
            int gks = kt*8 + ks;
            #pragma unroll
            for (int nt = 0; nt < 4; nt++) {
                float2 b = sB[(gks*32 + nt*8 + ln4)*4 + lc];
                mma_tf32(d[nt], a0, a1, a2, a3, __float_as_uint(b.x), __float_as_uint(b.y));
            }
        }
    }
    float* Gf = (float*)g_G;
    size_t rowg = (size_t)blockIdx.x*128 + r0 + ln4;
    #pragma unroll
    for (int nt = 0; nt < 4; nt++) {
        int col = nt*8 + 2*lc;
        *(float2*)&Gf[rowg*32 + col]       = make_float2(d[nt][0], d[nt][1]);
        *(float2*)&Gf[(rowg + 8)*32 + col] = make_float2(d[nt][2], d[nt][3]);
    }
}

// ---------------- stage 2: fwd h-DFT, radix-16, G read straight to registers ----------------
__global__ __launch_bounds__(256) void fwd_hdft() {
    __shared__ float2 sP[16*257];   // 32.9 KB exchange
    __shared__ float2 sTW[256];
    __shared__ float2 s16[16];
    int bi = blockIdx.x, tid = threadIdx.x;

    sTW[tid & 255] = g_TW256[tid & 255];
    if (tid < 16) s16[tid] = g_TW16[tid];

    // phase 1: coalesced direct gmem loads (element reuse = 1, no staging)
    const float2* Gsrc = &g_G[(size_t)bi * 4096];
    float2 g[16];
    #pragma unroll
    for (int h1 = 0; h1 < 16; h1++) g[h1] = Gsrc[h1*256 + tid];
    __syncthreads();

    int h0 = tid >> 4, ky = tid & 15;
    float2 P[16];
    #pragma unroll
    for (int a = 0; a < 16; a++) P[a] = make_float2(0.f, 0.f);
    #pragma unroll
    for (int h1 = 0; h1 < 16; h1++) {
        #pragma unroll
        for (int a = 0; a < 16; a++) {
            float2 t = s16[(a*h1) & 15];
            P[a].x += g[h1].x*t.x - g[h1].y*t.y;
            P[a].y += g[h1].x*t.y + g[h1].y*t.x;
        }
    }
    #pragma unroll
    for (int a = 0; a < 16; a++) sP[h0*257 + a*16 + ky] = P[a];
    __syncthreads();

    int a = h0;
    float2 x1 = make_float2(0.f, 0.f), x2 = make_float2(0.f, 0.f);
    #pragma unroll
    for (int hh = 0; hh < 16; hh++) {
        float2 p  = sP[hh*257 + a*16 + ky];
        float2 t1 = sTW[a*16 + hh];
        float2 q;
        q.x = p.x*t1.x - p.y*t1.y;
        q.y = p.x*t1.y + p.y*t1.x;
        x1.x += q.x; x1.y += q.y;
        float2 c = s16[hh];
        x2.x += q.x*c.x + q.y*c.y;
        x2.y += q.y*c.x - q.x*c.y;
    }
    g_Xft[(bi*32 + a)*16 + ky]      = x1;
    g_Xft[(bi*32 + 16 + a)*16 + ky] = x2;
}

// ---------------- stage 3: channel mix ----------------
__global__ __launch_bounds__(256) void chan_mix() {
    __shared__ float2 sW[32*32];
    __shared__ float2 sX[16*32];
    int mode  = blockIdx.x;
    int kxidx = mode >> 4, ky = mode & 15;
    int tid   = threadIdx.x;

    #pragma unroll
    for (int p = 0; p < 4; p++) sW[tid + p*256] = g_wpack[mode*1024 + tid + p*256];
    sX[tid % 512]         = g_Xft[(tid*32 + kxidx)*16 + ky];
    sX[(tid + 256) % 512] = g_Xft[((tid + 256)*32 + kxidx)*16 + ky];
    __syncthreads();

    int o = tid & 31, b0 = tid >> 5;
    float2 acc0 = make_float2(0.f, 0.f), acc1 = make_float2(0.f, 0.f);
    #pragma unroll
    for (int i = 0; i < 32; i++) {
        float2 wv = sW[i*32 + o];
        float2 x0 = sX[b0*32 + i];
        float2 x1 = sX[(b0 + 8)*32 + i];
        acc0.x += x0.x*wv.x - x0.y*wv.y; acc0.y += x0.x*wv.y + x0.y*wv.x;
        acc1.x += x1.x*wv.x - x1.y*wv.y; acc1.y += x1.x*wv.y + x1.y*wv.x;
    }
    g_Yft[((b0*32 + o)*32 + kxidx)*16 + ky]       = acc0;
    g_Yft[(((b0 + 8)*32 + o)*32 + kxidx)*16 + ky] = acc1;
}

// ---------------- stage 4+5 fused: inverse h-DFT (smem) + inverse w-DFT mma ----------------
// one CTA per (b,o): phase A builds Zp[256 h][32] in smem, phase B runs 8 MMA tiles M=32,N=256,K=32
__global__ __launch_bounds__(256) void inv_fused_mma(float* __restrict__ out) {
    extern __shared__ float s5[];
    float*  sZ  = s5;                          // [256][36] floats = 36864 B
    float2* sB  = (float2*)(s5 + 256*36);      // 4096 float2 = 32768 B
    float2* sY  = sB + 4096;                   // 512
    float2* sTW = sY + 512;                    // 256
    float2* s16 = sTW + 256;                   // 16
    int bo = blockIdx.x, tid = threadIdx.x;
    int wid = tid >> 5, lane = tid & 31;
    int ln4 = lane >> 2, lc = lane & 3;

    // loads
    const float2* gB = (const float2*)g_B5;
    #pragma unroll
    for (int p = 0; p < 16; p++) sB[tid + p*256] = gB[tid + p*256];
    sY[tid]       = g_Yft[bo*512 + tid];
    sY[tid + 256] = g_Yft[bo*512 + tid + 256];
    sTW[tid & 255] = g_TW256[tid & 255];
    if (tid < 16) s16[tid] = g_TW16[tid];
    __syncthreads();

    // ---- phase A: inverse h-DFT into sZ ----
    int h0 = tid >> 4, ky = tid & 15;
    {
        float2 w16 = s16[h0];
        float2 Q[16];
        #pragma unroll
        for (int j = 0; j < 16; j++) {
            float2 t = sTW[j*16 + h0];
            float2 u = make_float2(t.x, -t.y);
            float2 v;
            v.x = u.x*w16.x - u.y*w16.y;
            v.y = u.x*w16.y + u.y*w16.x;
            float2 y1 = sY[j*16 + ky], y2 = sY[(16 + j)*16 + ky];
            Q[j].x = y1.x*u.x - y1.y*u.y + y2.x*v.x - y2.y*v.y;
            Q[j].y = y1.x*u.y + y1.y*u.x + y2.x*v.y + y2.y*v.x;
        }
        #pragma unroll
        for (int h1 = 0; h1 < 16; h1++) {
            float2 acc = make_float2(0.f, 0.f);
            #pragma unroll
            for (int j = 0; j < 16; j++) {
                float2 t = s16[(j*h1) & 15];
                acc.x += Q[j].x*t.x + Q[j].y*t.y;
                acc.y += Q[j].y*t.x - Q[j].x*t.y;
            }
            int h = h1*16 + h0;
            *(float2*)&sZ[h*36 + 2*ky] = make_float2(tf32rna(acc.x), tf32rna(acc.y));
        }
    }
    __syncthreads();

    // ---- phase B: 8 MMA tiles (M=32 rows each), N=256, K=32 ----
    int warpM = wid >> 2, warpN = wid & 3;
    int r0 = warpM * 16, n00 = warpN * 64;
    for (int mt = 0; mt < 8; mt++) {
        int rbase = mt*32 + r0;
        float d[8][4] = {};
        #pragma unroll
        for (int ks = 0; ks < 4; ks++) {
            int kc = ks*8;
            uint32_t a0 = __float_as_uint(sZ[(rbase + ln4    )*36 + kc + lc    ]);
            uint32_t a1 = __float_as_uint(sZ[(rbase + ln4 + 8)*36 + kc + lc    ]);
            uint32_t a2 = __float_as_uint(sZ[(rbase + ln4    )*36 + kc + lc + 4]);
            uint32_t a3 = __float_as_uint(sZ[(rbase + ln4 + 8)*36 + kc + lc + 4]);
            #pragma unroll
            for (int nt = 0; nt < 8; nt++) {
                float2 b = sB[(ks*256 + n00 + nt*8 + ln4)*4 + lc];
                mma_tf32(d[nt], a0, a1, a2, a3, __float_as_uint(b.x), __float_as_uint(b.y));
            }
        }
        size_t rowg = (size_t)bo*256 + rbase + ln4;
        float* o0 = out + rowg*256;
        float* o1 = out + (rowg + 8)*256;
        #pragma unroll
        for (int nt = 0; nt < 8; nt++) {
            int col = n00 + nt*8 + 2*lc;
            *(float2*)&o0[col] = make_float2(d[nt][0], d[nt][1]);
            *(float2*)&o1[col] = make_float2(d[nt][2], d[nt][3]);
        }
    }
}

// ---------------- launch ----------------
extern "C" void kernel_launch(void* const* d_in, const int* in_sizes, int n_in,
                              void* d_out, int out_size) {
    const float* x   = (const float*)d_in[0];
    const float* w1r = (const float*)d_in[1];
    const float* w1i = (const float*)d_in[2];
    const float* w2r = (const float*)d_in[3];
    const float* w2i = (const float*)d_in[4];
    float* out = (float*)d_out;

    const int FW_SMEM = (128*68)*4 + 4096*8;                      // 67584
    const int IV_SMEM = 256*36*4 + 4096*8 + (512+256+16)*8;       // 75904
    cudaFuncSetAttribute(fwd_wdft_mma,  cudaFuncAttributeMaxDynamicSharedMemorySize, FW_SMEM);
    cudaFuncSetAttribute(inv_fused_mma, cudaFuncAttributeMaxDynamicSharedMemorySize, IV_SMEM);

    init_tables<<<34, 256>>>();
    repack_w<<<2048, 256>>>(w1r, w1i, w2r, w2i);
    fwd_wdft_mma<<<RFW/128, 256, FW_SMEM>>>(x);
    fwd_hdft<<<BB*CIN, 256>>>();
    chan_mix<<<512, 256>>>();
    inv_fused_mma<<<BB*COUT, 256, IV_SMEM>>>(out);
}